// round 5
// baseline (speedup 1.0000x reference)
#include <cuda_runtime.h>
#include <math.h>

#define BATCH 65536
#define IN_DIM 64
#define HID 128
#define CHOL 136
#define FULLM 0xffffffffu

// Scratch
__device__ float g_h1[BATCH * HID];
__device__ float g_h2[BATCH * HID];
__device__ float g_ld[BATCH * CHOL];

// ---------------------------------------------------------------------------
// Tiled SGEMM with fused bias + activation.  C[M,N] = act(A[M,K] @ W[K,N] + b)
// ---------------------------------------------------------------------------
template<int ACT>
__global__ __launch_bounds__(256) void gemm_bias_act(
    const float* __restrict__ A, const float* __restrict__ W,
    const float* __restrict__ bias, float* __restrict__ C,
    int M, int N, int K)
{
    __shared__ float sA[64][17];
    __shared__ float sW[16][64];
    const int tid = threadIdx.x;
    const int tx = tid & 15, ty = tid >> 4;
    const int bm = blockIdx.x * 64, bn = blockIdx.y * 64;

    float acc[4][4] = {};

    for (int k0 = 0; k0 < K; k0 += 16) {
        #pragma unroll
        for (int i = 0; i < 4; i++) {
            int idx = tid + i * 256;
            int m = idx >> 4, kk = idx & 15;
            sA[m][kk] = A[(size_t)(bm + m) * K + (k0 + kk)];
        }
        #pragma unroll
        for (int i = 0; i < 4; i++) {
            int idx = tid + i * 256;
            int kk = idx >> 6, n = idx & 63;
            int col = bn + n;
            sW[kk][n] = (col < N) ? W[(size_t)(k0 + kk) * N + col] : 0.f;
        }
        __syncthreads();
        #pragma unroll
        for (int kk = 0; kk < 16; kk++) {
            float a[4], bb[4];
            #pragma unroll
            for (int i = 0; i < 4; i++) a[i] = sA[ty * 4 + i][kk];
            #pragma unroll
            for (int j = 0; j < 4; j++) bb[j] = sW[kk][tx * 4 + j];
            #pragma unroll
            for (int i = 0; i < 4; i++)
                #pragma unroll
                for (int j = 0; j < 4; j++)
                    acc[i][j] = fmaf(a[i], bb[j], acc[i][j]);
        }
        __syncthreads();
    }

    #pragma unroll
    for (int i = 0; i < 4; i++) {
        int row = bm + ty * 4 + i;
        #pragma unroll
        for (int j = 0; j < 4; j++) {
            int col = bn + tx * 4 + j;
            if (col < N) {
                float v = acc[i][j] + bias[col];
                if (ACT == 0) v = (v > 0.f) ? v : 0.01f * v;
                else          v = tanhf(v);
                C[(size_t)row * N + col] = v;
            }
        }
    }
}

// ---------------------------------------------------------------------------
// Eigendecomposition-free PSD head:
//   out = Ct / sqrt(tr(Ct^2)),  Ct = exp((B - I)/2),  B = exp(Q)^2.
// Lane c owns column c; multiplier matrix in smem (float4 rows, stride 20;
// matrix stride 336 words keeps the two warp-halves on disjoint banks).
// ---------------------------------------------------------------------------
#define MSTRIDE 336
#define RSTRIDE 20
#define NTERMS 6   // Taylor degree; err <= ||X||^7/7! (tiny for ||X||<0.5)

__device__ __forceinline__ void matvec16(const float* __restrict__ X,
                                         const float* __restrict__ s,
                                         float* __restrict__ acc)
{
    #pragma unroll
    for (int r = 0; r < 16; r++) {
        const float4* row = (const float4*)(X + r * RSTRIDE);
        float4 x0 = row[0], x1 = row[1], x2 = row[2], x3 = row[3];
        // two independent chains for ILP
        float a0 = x0.x * s[0];
        float a1 = x0.y * s[1];
        a0 = fmaf(x0.z, s[2],  a0);  a1 = fmaf(x0.w, s[3],  a1);
        a0 = fmaf(x1.x, s[4],  a0);  a1 = fmaf(x1.y, s[5],  a1);
        a0 = fmaf(x1.z, s[6],  a0);  a1 = fmaf(x1.w, s[7],  a1);
        a0 = fmaf(x2.x, s[8],  a0);  a1 = fmaf(x2.y, s[9],  a1);
        a0 = fmaf(x2.z, s[10], a0);  a1 = fmaf(x2.w, s[11], a1);
        a0 = fmaf(x3.x, s[12], a0);  a1 = fmaf(x3.y, s[13], a1);
        a0 = fmaf(x3.z, s[14], a0);  a1 = fmaf(x3.w, s[15], a1);
        acc[r] = a0 + a1;
    }
}

__global__ __launch_bounds__(256, 3) void psd_expm(
    const float* __restrict__ ldata, float* __restrict__ out)
{
    __shared__ __align__(16) float sh[16 * MSTRIDE];   // 21504 B
    const int tid = threadIdx.x;
    const int m   = tid >> 4;
    const int c   = tid & 15;
    const int b   = blockIdx.x * 16 + m;
    float* X = sh + m * MSTRIDE;

    // Stage the 136 tanh values.
    const float* rowp = ldata + (size_t)b * CHOL;
    #pragma unroll
    for (int j = c; j < CHOL; j += 16) X[j] = rowp[j];
    __syncwarp();

    // Build column c of Q = L + L^T (tril row-major idx(r,c) = r(r+1)/2 + c).
    float s[16], acc[16];
    #pragma unroll
    for (int r = 0; r < 16; r++) {
        int hi = (r > c) ? r : c;
        int lo = r + c - hi;
        float val = X[hi * (hi + 1) / 2 + lo];
        s[r] = (r == c) ? 2.f * val : val;
    }
    __syncwarp();
    #pragma unroll
    for (int r = 0; r < 16; r++) X[r * RSTRIDE + c] = s[r];

    // P = exp(Q): Horner  S = I + (X/k) S, start S = I + X/NTERMS.
    #pragma unroll
    for (int r = 0; r < 16; r++)
        s[r] = s[r] * (1.f / NTERMS) + ((r == c) ? 1.f : 0.f);
    __syncwarp();
    #pragma unroll
    for (int k = NTERMS - 1; k >= 1; k--) {
        matvec16(X, s, acc);
        float invk = 1.f / k;
        #pragma unroll
        for (int r = 0; r < 16; r++)
            s[r] = acc[r] * invk + ((r == c) ? 1.f : 0.f);
    }

    // B = P^2 : publish P, then b_c = P * p_c.
    __syncwarp();
    #pragma unroll
    for (int r = 0; r < 16; r++) X[r * RSTRIDE + c] = s[r];
    __syncwarp();
    matvec16(X, s, acc);                 // acc = column c of B

    // X2 = (B - I)/2 ; publish.
    #pragma unroll
    for (int r = 0; r < 16; r++)
        acc[r] = (acc[r] - ((r == c) ? 1.f : 0.f)) * 0.5f;
    __syncwarp();
    #pragma unroll
    for (int r = 0; r < 16; r++) X[r * RSTRIDE + c] = acc[r];

    // Ct = exp(X2), same Horner.
    #pragma unroll
    for (int r = 0; r < 16; r++)
        s[r] = acc[r] * (1.f / NTERMS) + ((r == c) ? 1.f : 0.f);
    __syncwarp();
    #pragma unroll
    for (int k = NTERMS - 1; k >= 1; k--) {
        matvec16(X, s, acc);
        float invk = 1.f / k;
        #pragma unroll
        for (int r = 0; r < 16; r++)
            s[r] = acc[r] * invk + ((r == c) ? 1.f : 0.f);
    }

    // scale = rsqrt(tr(Ct^2)) = rsqrt(sum_ij Ct_ij^2)  (Ct symmetric)
    float t = 0.f;
    #pragma unroll
    for (int r = 0; r < 16; r++) t = fmaf(s[r], s[r], t);
    #pragma unroll
    for (int o = 8; o; o >>= 1) t += __shfl_xor_sync(FULLM, t, o);
    float scale = rsqrtf(t);

    float* op = out + (size_t)b * 256;
    #pragma unroll
    for (int r = 0; r < 16; r++) op[r * 16 + c] = s[r] * scale;
}

// ---------------------------------------------------------------------------
extern "C" void kernel_launch(void* const* d_in, const int* in_sizes, int n_in,
                              void* d_out, int out_size)
{
    const float* x  = (const float*)d_in[0];
    const float* W1 = (const float*)d_in[1];
    const float* b1 = (const float*)d_in[2];
    const float* W2 = (const float*)d_in[3];
    const float* b2 = (const float*)d_in[4];
    const float* W3 = (const float*)d_in[5];
    const float* b3 = (const float*)d_in[6];
    float* out = (float*)d_out;

    float *h1, *h2, *ldp;
    cudaGetSymbolAddress((void**)&h1,  g_h1);
    cudaGetSymbolAddress((void**)&h2,  g_h2);
    cudaGetSymbolAddress((void**)&ldp, g_ld);

    dim3 blk(256);
    gemm_bias_act<0><<<dim3(BATCH / 64, (HID  + 63) / 64), blk>>>(x,  W1, b1, h1,  BATCH, HID,  IN_DIM);
    gemm_bias_act<0><<<dim3(BATCH / 64, (HID  + 63) / 64), blk>>>(h1, W2, b2, h2,  BATCH, HID,  HID);
    gemm_bias_act<1><<<dim3(BATCH / 64, (CHOL + 63) / 64), blk>>>(h2, W3, b3, ldp, BATCH, CHOL, HID);
    psd_expm<<<BATCH / 16, 256>>>(ldp, out);
}

// round 6
// speedup vs baseline: 1.4071x; 1.4071x over previous
#include <cuda_runtime.h>
#include <math.h>

#define BATCH 65536
#define IN_DIM 64
#define HID 128
#define CHOL 136
#define FULLM 0xffffffffu

// Scratch
__device__ float g_h1[BATCH * HID];
__device__ float g_h2[BATCH * HID];
__device__ float g_ld[BATCH * CHOL];

// ---------------------------------------------------------------------------
// Tiled SGEMM with fused bias + activation.  C[M,N] = act(A[M,K] @ W[K,N] + b)
// ---------------------------------------------------------------------------
template<int ACT>
__global__ __launch_bounds__(256) void gemm_bias_act(
    const float* __restrict__ A, const float* __restrict__ W,
    const float* __restrict__ bias, float* __restrict__ C,
    int M, int N, int K)
{
    __shared__ float sA[64][17];
    __shared__ float sW[16][64];
    const int tid = threadIdx.x;
    const int tx = tid & 15, ty = tid >> 4;
    const int bm = blockIdx.x * 64, bn = blockIdx.y * 64;

    float acc[4][4] = {};

    for (int k0 = 0; k0 < K; k0 += 16) {
        #pragma unroll
        for (int i = 0; i < 4; i++) {
            int idx = tid + i * 256;
            int m = idx >> 4, kk = idx & 15;
            sA[m][kk] = A[(size_t)(bm + m) * K + (k0 + kk)];
        }
        #pragma unroll
        for (int i = 0; i < 4; i++) {
            int idx = tid + i * 256;
            int kk = idx >> 6, n = idx & 63;
            int col = bn + n;
            sW[kk][n] = (col < N) ? W[(size_t)(k0 + kk) * N + col] : 0.f;
        }
        __syncthreads();
        #pragma unroll
        for (int kk = 0; kk < 16; kk++) {
            float a[4], bb[4];
            #pragma unroll
            for (int i = 0; i < 4; i++) a[i] = sA[ty * 4 + i][kk];
            #pragma unroll
            for (int j = 0; j < 4; j++) bb[j] = sW[kk][tx * 4 + j];
            #pragma unroll
            for (int i = 0; i < 4; i++)
                #pragma unroll
                for (int j = 0; j < 4; j++)
                    acc[i][j] = fmaf(a[i], bb[j], acc[i][j]);
        }
        __syncthreads();
    }

    #pragma unroll
    for (int i = 0; i < 4; i++) {
        int row = bm + ty * 4 + i;
        #pragma unroll
        for (int j = 0; j < 4; j++) {
            int col = bn + tx * 4 + j;
            if (col < N) {
                float v = acc[i][j] + bias[col];
                if (ACT == 0) v = (v > 0.f) ? v : 0.01f * v;
                else          v = tanhf(v);
                C[(size_t)row * N + col] = v;
            }
        }
    }
}

// ---------------------------------------------------------------------------
// Eigendecomposition-free PSD head:
//   out = Ct / sqrt(tr(Ct^2)),  Ct = exp((B - I)/2),  B = exp(Q)^2.
// Lane c owns column c; multiplier matrix in smem (float4 rows, stride 20;
// matrix stride 336 words keeps the two warp-halves on disjoint banks).
// Horner loops deliberately NOT unrolled -> one matvec's temporaries live
// at a time -> fits in 84 regs (3 CTAs/SM) without spilling.
// ---------------------------------------------------------------------------
#define MSTRIDE 336
#define RSTRIDE 20
#define NTERMS 6   // Taylor degree; err <= ||X||^7/7!

__constant__ float c_invk[NTERMS] = {0.f, 1.f, 0.5f, 1.f/3.f, 0.25f, 0.2f};

__device__ __forceinline__ void matvec16(const float* __restrict__ X,
                                         const float* __restrict__ s,
                                         float* __restrict__ acc)
{
    #pragma unroll
    for (int r = 0; r < 16; r++) {
        const float4* row = (const float4*)(X + r * RSTRIDE);
        float4 x0 = row[0], x1 = row[1], x2 = row[2], x3 = row[3];
        float a0 = x0.x * s[0];
        float a1 = x0.y * s[1];
        a0 = fmaf(x0.z, s[2],  a0);  a1 = fmaf(x0.w, s[3],  a1);
        a0 = fmaf(x1.x, s[4],  a0);  a1 = fmaf(x1.y, s[5],  a1);
        a0 = fmaf(x1.z, s[6],  a0);  a1 = fmaf(x1.w, s[7],  a1);
        a0 = fmaf(x2.x, s[8],  a0);  a1 = fmaf(x2.y, s[9],  a1);
        a0 = fmaf(x2.z, s[10], a0);  a1 = fmaf(x2.w, s[11], a1);
        a0 = fmaf(x3.x, s[12], a0);  a1 = fmaf(x3.y, s[13], a1);
        a0 = fmaf(x3.z, s[14], a0);  a1 = fmaf(x3.w, s[15], a1);
        acc[r] = a0 + a1;
    }
}

__global__ __launch_bounds__(256, 3) void psd_expm(
    const float* __restrict__ ldata, float* __restrict__ out)
{
    __shared__ __align__(16) float sh[16 * MSTRIDE];   // 21504 B
    const int tid = threadIdx.x;
    const int m   = tid >> 4;
    const int c   = tid & 15;
    const int b   = blockIdx.x * 16 + m;
    float* X = sh + m * MSTRIDE;

    // Stage the 136 tanh values.
    const float* rowp = ldata + (size_t)b * CHOL;
    #pragma unroll
    for (int j = c; j < CHOL; j += 16) X[j] = rowp[j];
    __syncwarp();

    // Build column c of Q = L + L^T (tril row-major idx(r,c) = r(r+1)/2 + c).
    float s[16], acc[16];
    #pragma unroll
    for (int r = 0; r < 16; r++) {
        int hi = (r > c) ? r : c;
        int lo = r + c - hi;
        float val = X[hi * (hi + 1) / 2 + lo];
        s[r] = (r == c) ? 2.f * val : val;
    }
    __syncwarp();
    #pragma unroll
    for (int r = 0; r < 16; r++) X[r * RSTRIDE + c] = s[r];

    // P = exp(Q): Horner  S = I + (X/k) S, start S = I + X/NTERMS.
    #pragma unroll
    for (int r = 0; r < 16; r++)
        s[r] = s[r] * (1.f / NTERMS) + ((r == c) ? 1.f : 0.f);
    __syncwarp();
    #pragma unroll 1
    for (int k = NTERMS - 1; k >= 1; k--) {
        matvec16(X, s, acc);
        float invk = c_invk[k];
        #pragma unroll
        for (int r = 0; r < 16; r++)
            s[r] = acc[r] * invk + ((r == c) ? 1.f : 0.f);
    }

    // B = P^2 : publish P, then b_c = P * p_c.
    __syncwarp();
    #pragma unroll
    for (int r = 0; r < 16; r++) X[r * RSTRIDE + c] = s[r];
    __syncwarp();
    matvec16(X, s, acc);                 // acc = column c of B

    // X2 = (B - I)/2 ; publish.
    #pragma unroll
    for (int r = 0; r < 16; r++)
        acc[r] = (acc[r] - ((r == c) ? 1.f : 0.f)) * 0.5f;
    __syncwarp();
    #pragma unroll
    for (int r = 0; r < 16; r++) X[r * RSTRIDE + c] = acc[r];

    // Ct = exp(X2), same Horner.
    #pragma unroll
    for (int r = 0; r < 16; r++)
        s[r] = acc[r] * (1.f / NTERMS) + ((r == c) ? 1.f : 0.f);
    __syncwarp();
    #pragma unroll 1
    for (int k = NTERMS - 1; k >= 1; k--) {
        matvec16(X, s, acc);
        float invk = c_invk[k];
        #pragma unroll
        for (int r = 0; r < 16; r++)
            s[r] = acc[r] * invk + ((r == c) ? 1.f : 0.f);
    }

    // scale = rsqrt(tr(Ct^2)) = rsqrt(sum_ij Ct_ij^2)  (Ct symmetric)
    float t = 0.f;
    #pragma unroll
    for (int r = 0; r < 16; r++) t = fmaf(s[r], s[r], t);
    #pragma unroll
    for (int o = 8; o; o >>= 1) t += __shfl_xor_sync(FULLM, t, o);
    float scale = rsqrtf(t);

    float* op = out + (size_t)b * 256;
    #pragma unroll
    for (int r = 0; r < 16; r++) op[r * 16 + c] = s[r] * scale;
}

// ---------------------------------------------------------------------------
extern "C" void kernel_launch(void* const* d_in, const int* in_sizes, int n_in,
                              void* d_out, int out_size)
{
    const float* x  = (const float*)d_in[0];
    const float* W1 = (const float*)d_in[1];
    const float* b1 = (const float*)d_in[2];
    const float* W2 = (const float*)d_in[3];
    const float* b2 = (const float*)d_in[4];
    const float* W3 = (const float*)d_in[5];
    const float* b3 = (const float*)d_in[6];
    float* out = (float*)d_out;

    float *h1, *h2, *ldp;
    cudaGetSymbolAddress((void**)&h1,  g_h1);
    cudaGetSymbolAddress((void**)&h2,  g_h2);
    cudaGetSymbolAddress((void**)&ldp, g_ld);

    dim3 blk(256);
    gemm_bias_act<0><<<dim3(BATCH / 64, (HID  + 63) / 64), blk>>>(x,  W1, b1, h1,  BATCH, HID,  IN_DIM);
    gemm_bias_act<0><<<dim3(BATCH / 64, (HID  + 63) / 64), blk>>>(h1, W2, b2, h2,  BATCH, HID,  HID);
    gemm_bias_act<1><<<dim3(BATCH / 64, (CHOL + 63) / 64), blk>>>(h2, W3, b3, ldp, BATCH, CHOL, HID);
    psd_expm<<<BATCH / 16, 256>>>(ldp, out);
}